// round 16
// baseline (speedup 1.0000x reference)
#include <cuda_runtime.h>
#include <cuda_bf16.h>
#include <stdint.h>
#include <math.h>

#define NN 8192
#define EE 65536
#define LAT 128
#define WRS_LD 944
#define UCOLS 816
#define ENVN 48
#define MULN 16
#define SPHN 9
#define QKN 256
#define EPSF 1e-5f

// ---------- static scratch ----------
__device__ float    g_U[NN * UCOLS];
__device__ float    g_Kn[NN * QKN];
__device__ float    g_dh[NN * LAT];
__device__ float    g_envw[(size_t)EE * ENVN];
__device__ float    g_x[(size_t)EE * 144];
__device__ float    g_scores[EE * MULN];
__device__ unsigned g_maxb[NN * MULN];
__device__ float    g_den[NN * MULN];
__device__ float    g_dX[NN * MULN * SPHN];
// 19 pre-converted B tiles: 0-6 W_rs[:, :816], 7-8 W_query (unused now),
// 9 W1, 10-11 W_key, 12-18 W2[:, :816]
__device__ __nv_bfloat16 g_Whi[19 * 128 * 128];
__device__ __nv_bfloat16 g_Wlo[19 * 128 * 128];

__device__ __forceinline__ unsigned fenc(float f) {
    unsigned u = __float_as_uint(f);
    return (u & 0x80000000u) ? ~u : (u | 0x80000000u);
}
__device__ __forceinline__ float fdec(unsigned u) {
    return (u & 0x80000000u) ? __uint_as_float(u & 0x7FFFFFFFu)
                             : __uint_as_float(~u);
}

__global__ void init_kernel() {
    int i = blockIdx.x * blockDim.x + threadIdx.x;
    int stride = gridDim.x * blockDim.x;
    for (int t = i; t < NN * LAT; t += stride) g_dh[t] = 0.f;
    for (int t = i; t < EE * MULN; t += stride) g_scores[t] = 0.f;
    for (int t = i; t < NN * MULN; t += stride) { g_den[t] = 0.f; g_maxb[t] = 0u; }
    for (int t = i; t < NN * MULN * SPHN; t += stride) g_dX[t] = 0.f;
}

__device__ __forceinline__ uint32_t pack_hi2(float x, float y, float& lx, float& ly) {
    __nv_bfloat16 bx = __float2bfloat16(x), by = __float2bfloat16(y);
    lx = x - __bfloat162float(bx);
    ly = y - __bfloat162float(by);
    return ((uint32_t)__bfloat16_as_ushort(by) << 16) | __bfloat16_as_ushort(bx);
}
__device__ __forceinline__ uint32_t pack_bf2(float x, float y) {
    return ((uint32_t)__bfloat16_as_ushort(__float2bfloat16(y)) << 16)
         | __bfloat16_as_ushort(__float2bfloat16(x));
}

// ---------- one-time W conversion ----------
__global__ void wprep_kernel(const float* __restrict__ Wrs, const float* __restrict__ Wq,
                             const float* __restrict__ W1,  const float* __restrict__ Wk,
                             const float* __restrict__ W2) {
    int idx = blockIdx.x * blockDim.x + threadIdx.x;
    if (idx >= 19 * 128 * 32) return;
    int tile = idx >> 12;
    int rem = idx & 4095;
    int kk = rem >> 5, n4 = (rem & 31) << 2;
    int width = 128;
    const float* src = nullptr;
    size_t ld = 0; int base = 0;
    if (tile < 7)       { src = Wrs; ld = WRS_LD; base = tile * 128; if (tile == 6) width = 48; }
    else if (tile < 9)  { src = Wq;  ld = QKN;    base = (tile - 7) * 128; }
    else if (tile == 9) { src = W1;  ld = 128;    base = 0; }
    else if (tile < 12) { src = Wk;  ld = QKN;    base = (tile - 10) * 128; }
    else                { src = W2;  ld = WRS_LD; base = (tile - 12) * 128; if (tile == 18) width = 48; }
    float4 w = make_float4(0.f, 0.f, 0.f, 0.f);
    if (n4 < width) w = *(const float4*)(src + (size_t)kk * ld + base + n4);
    float lx, ly, lz, lw;
    uint32_t h01 = pack_hi2(w.x, w.y, lx, ly);
    uint32_t h23 = pack_hi2(w.z, w.w, lz, lw);
    size_t o = (size_t)tile * 16384 + kk * 128 + n4;
    *(uint2*)(g_Whi + o) = make_uint2(h01, h23);
    *(uint2*)(g_Wlo + o) = make_uint2(pack_bf2(lx, ly), pack_bf2(lz, lw));
}

// ============================================================
// MMA helpers
// ============================================================
__device__ __forceinline__ void mma16816(float* c, const uint32_t* a, const uint32_t* b) {
    asm volatile(
        "mma.sync.aligned.m16n8k16.row.col.f32.bf16.bf16.f32 "
        "{%0,%1,%2,%3}, {%4,%5,%6,%7}, {%8,%9}, {%0,%1,%2,%3};"
        : "+f"(c[0]), "+f"(c[1]), "+f"(c[2]), "+f"(c[3])
        : "r"(a[0]), "r"(a[1]), "r"(a[2]), "r"(a[3]), "r"(b[0]), "r"(b[1]));
}
__device__ __forceinline__ void ldsm_x4_trans(uint32_t* d, uint32_t addr) {
    asm volatile("ldmatrix.sync.aligned.m8n8.x4.trans.shared.b16 {%0,%1,%2,%3}, [%4];"
                 : "=r"(d[0]), "=r"(d[1]), "=r"(d[2]), "=r"(d[3]) : "r"(addr));
}
__device__ __forceinline__ void ldsm_x4(uint32_t* d, uint32_t addr) {
    asm volatile("ldmatrix.sync.aligned.m8n8.x4.shared.b16 {%0,%1,%2,%3}, [%4];"
                 : "=r"(d[0]), "=r"(d[1]), "=r"(d[2]), "=r"(d[3]) : "r"(addr));
}
__device__ __forceinline__ uint32_t smem_u32(const void* p) {
    uint32_t a;
    asm("{ .reg .u64 t; cvta.to.shared.u64 t, %1; cvt.u32.u64 %0, t; }" : "=r"(a) : "l"(p));
    return a;
}
#define CP_ASYNC16(dst, src) \
    asm volatile("cp.async.cg.shared.global [%0], [%1], 16;" :: "r"(dst), "l"(src))
#define CP_COMMIT() asm volatile("cp.async.commit_group;" ::: "memory")
#define CP_WAIT0()  asm volatile("cp.async.wait_group 0;" ::: "memory")

#define LDK 136
#define LDN 136

// ============================================================
// fused node kernel (unchanged from R13)
// ============================================================
#define NATB (64 * LDK * 2)
#define NBTB (128 * LDN * 2)
#define NOFF_AHI  0
#define NOFF_ALO  (NOFF_AHI + NATB)
#define NOFF_SHI  (NOFF_ALO + NATB)
#define NOFF_SLO  (NOFF_SHI + NATB)
#define NOFF_BHI  (NOFF_SLO + NATB)
#define NOFF_BLO  (NOFF_BHI + NBTB)
#define SMEM_NODE (NOFF_BLO + NBTB)

__global__ void __launch_bounds__(512, 1) node_mma_kernel(const float* __restrict__ h)
{
    extern __shared__ char smem[];
    const int tid = threadIdx.x, wid = tid >> 5, lane = tid & 31;
    const int gid = lane >> 2, tig = lane & 3;
    const int bm = blockIdx.x << 6;
    const uint32_t sb = smem_u32(smem);

    for (int idx = tid; idx < 64 * 32; idx += 512) {
        int r = idx >> 5, c4 = (idx & 31) << 2;
        float4 v = *(const float4*)(h + (size_t)(bm + r) * 128 + c4);
        float lx, ly, lz, lw;
        uint32_t h01 = pack_hi2(v.x, v.y, lx, ly);
        uint32_t h23 = pack_hi2(v.z, v.w, lz, lw);
        int boff = r * (LDK * 2) + c4 * 2;
        *(uint2*)(smem + NOFF_AHI + boff) = make_uint2(h01, h23);
        *(uint2*)(smem + NOFF_ALO + boff) = make_uint2(pack_bf2(lx, ly), pack_bf2(lz, lw));
    }

    const int wm = (wid & 3) << 4;
    const int wn = (wid >> 2) << 5;
    const int rr0 = wm + gid, rr1 = rr0 + 8;
    const int arow = wm + (lane & 15);
    const int acolb = ((lane >> 4) << 3) * 2;

    for (int ph = 0; ph < 10; ph++) {
        int wtile;
        uint32_t aoffH, aoffL;
        if (ph == 0)      { wtile = 9;            aoffH = NOFF_AHI; aoffL = NOFF_ALO; }
        else if (ph < 8)  { wtile = 12 + ph - 1;  aoffH = NOFF_SHI; aoffL = NOFF_SLO; }
        else              { wtile = 10 + ph - 8;  aoffH = NOFF_AHI; aoffL = NOFF_ALO; }
        int width = (wtile == 18) ? 48 : 128;

        {
            const __nv_bfloat16* sh = g_Whi + (size_t)wtile * 16384;
            const __nv_bfloat16* sl = g_Wlo + (size_t)wtile * 16384;
            for (int idx = tid; idx < 128 * 16; idx += 512) {
                int kk = idx >> 4, n8 = (idx & 15) << 3;
                int boff = kk * (LDN * 2) + n8 * 2;
                *(uint4*)(smem + NOFF_BHI + boff) = *(const uint4*)(sh + kk * 128 + n8);
                *(uint4*)(smem + NOFF_BLO + boff) = *(const uint4*)(sl + kk * 128 + n8);
            }
        }
        __syncthreads();

        float acc[4][4];
#pragma unroll
        for (int ni = 0; ni < 4; ni++)
#pragma unroll
            for (int q = 0; q < 4; q++) acc[ni][q] = 0.f;

#pragma unroll
        for (int ks = 0; ks < 8; ks++) {
            const int k0 = ks << 4;
            uint32_t ahi[4], alo[4];
            const uint32_t aaddr = (uint32_t)(arow * (LDK * 2) + k0 * 2 + acolb);
            ldsm_x4(ahi, sb + aoffH + aaddr);
            ldsm_x4(alo, sb + aoffL + aaddr);
            const uint32_t rowb = (uint32_t)((k0 + (lane & 15)) * (LDN * 2) + ((lane >> 4) << 4));
#pragma unroll
            for (int ni = 0; ni < 4; ni += 2) {
                const uint32_t nb = (uint32_t)((wn + (ni << 3)) * 2);
                uint32_t bh[4], bl[4];
                ldsm_x4_trans(bh, sb + NOFF_BHI + rowb + nb);
                ldsm_x4_trans(bl, sb + NOFF_BLO + rowb + nb);
                mma16816(acc[ni],   ahi, bh);     mma16816(acc[ni],   ahi, bl);
                mma16816(acc[ni],   alo, bh);
                mma16816(acc[ni+1], ahi, bh + 2); mma16816(acc[ni+1], ahi, bl + 2);
                mma16816(acc[ni+1], alo, bh + 2);
            }
        }
        __syncthreads();

        if (ph == 0) {
#pragma unroll
            for (int ni = 0; ni < 4; ni++) {
                int c = wn + (ni << 3) + (tig << 1);
                float v0 = acc[ni][0] / (1.f + expf(-acc[ni][0]));
                float v1 = acc[ni][1] / (1.f + expf(-acc[ni][1]));
                float v2 = acc[ni][2] / (1.f + expf(-acc[ni][2]));
                float v3 = acc[ni][3] / (1.f + expf(-acc[ni][3]));
                float l0, l1, l2, l3;
                uint32_t h01 = pack_hi2(v0, v1, l0, l1);
                uint32_t h23 = pack_hi2(v2, v3, l2, l3);
                *(uint32_t*)(smem + NOFF_SHI + rr0 * (LDK*2) + c * 2) = h01;
                *(uint32_t*)(smem + NOFF_SHI + rr1 * (LDK*2) + c * 2) = h23;
                *(uint32_t*)(smem + NOFF_SLO + rr0 * (LDK*2) + c * 2) = pack_bf2(l0, l1);
                *(uint32_t*)(smem + NOFF_SLO + rr1 * (LDK*2) + c * 2) = pack_bf2(l2, l3);
            }
            __syncthreads();
        } else if (ph < 8) {
            int base = (ph - 1) * 128;
#pragma unroll
            for (int ni = 0; ni < 4; ni++) {
                int c = wn + (ni << 3) + (tig << 1);
                if (c < width) {
                    *(float2*)(g_U + (size_t)(bm + rr0) * UCOLS + base + c)
                        = make_float2(acc[ni][0], acc[ni][1]);
                    *(float2*)(g_U + (size_t)(bm + rr1) * UCOLS + base + c)
                        = make_float2(acc[ni][2], acc[ni][3]);
                }
            }
        } else {
            int base = (ph - 8) * 128;
#pragma unroll
            for (int ni = 0; ni < 4; ni++) {
                int c = wn + (ni << 3) + (tig << 1);
                *(float2*)(g_Kn + (size_t)(bm + rr0) * QKN + base + c)
                    = make_float2(acc[ni][0], acc[ni][1]);
                *(float2*)(g_Kn + (size_t)(bm + rr1) * QKN + base + c)
                    = make_float2(acc[ni][2], acc[ni][3]);
            }
        }
    }
}

// ============================================================
// HYBRID edge kernel: bid%3<2 -> tensor path (tiles 0..6);
// bid%3==2 -> fp32 FMA path (QK scores) on the idle fma pipe.
// ============================================================
#define ATB (32 * LDK * 2)
#define BTB (128 * LDN * 2)
#define OFF_J     0
#define OFF_CT    128
#define OFF_AHI   1792
#define OFF_ALO   (OFF_AHI + ATB)
#define OFF_BHI   (OFF_ALO + ATB)
#define OFF_BLO   (OFF_BHI + BTB)
#define OFF_XS    (OFF_BLO + BTB)
#define SMEM_EDGE (OFF_XS + 32*148*4)      // 107776

__global__ void __launch_bounds__(256, 2) edge_hybrid_kernel(
    const float* __restrict__ T, const int* __restrict__ ectr,
    const int* __restrict__ enb, const float* __restrict__ X,
    const float* __restrict__ Wq)
{
    extern __shared__ char smem[];
    const int tid = threadIdx.x;
    const int bid = blockIdx.x;
    const int sel = bid % 3;

    if (sel == 2) {
        // ================= FMA path: QK scores (R3-proven SGEMM) =============
        float* As = (float*)smem;               // [16][132]
        float* Bs = (float*)(smem + 16*132*4);  // [16][132]
        const int fid = bid / 3;                // 0..1023
        const int qt = fid & 1;                 // N-tile: 0 or 1
        const int qoff = qt << 7;
        const int bm = (fid >> 1) << 7;         // 128 edges
        const int tx = tid & 15, ty = tid >> 4;
        float acc[8][8];
#pragma unroll
        for (int i = 0; i < 8; i++)
#pragma unroll
            for (int j = 0; j < 8; j++) acc[i][j] = 0.f;

        for (int k0 = 0; k0 < 128; k0 += 16) {
#pragma unroll
            for (int hh = 0; hh < 2; hh++) {
                int t = tid + hh * 256;
                int r = t >> 2, kq = (t & 3) << 2;
                float4 av = *(const float4*)(T + (size_t)(bm + r) * 128 + k0 + kq);
                As[(kq + 0) * 132 + r] = av.x; As[(kq + 1) * 132 + r] = av.y;
                As[(kq + 2) * 132 + r] = av.z; As[(kq + 3) * 132 + r] = av.w;
            }
#pragma unroll
            for (int hh = 0; hh < 2; hh++) {
                int t = tid + hh * 256;
                int kr = t >> 5, c4 = (t & 31) << 2;
                float4 bv = *(const float4*)(Wq + (size_t)(k0 + kr) * QKN + qoff + c4);
                *(float4*)&Bs[kr * 132 + c4] = bv;
            }
            __syncthreads();
#pragma unroll
            for (int kk = 0; kk < 16; kk++) {
                float a[8], b[8];
                *(float4*)(a + 0) = *(const float4*)&As[kk * 132 + (ty << 2)];
                *(float4*)(a + 4) = *(const float4*)&As[kk * 132 + 64 + (ty << 2)];
                *(float4*)(b + 0) = *(const float4*)&Bs[kk * 132 + (tx << 2)];
                *(float4*)(b + 4) = *(const float4*)&Bs[kk * 132 + 64 + (tx << 2)];
#pragma unroll
                for (int i = 0; i < 8; i++)
#pragma unroll
                    for (int j = 0; j < 8; j++) acc[i][j] += a[i] * b[j];
            }
            __syncthreads();
        }
        // epilogue: Q.K -> scores
#pragma unroll
        for (int ih = 0; ih < 2; ih++)
#pragma unroll
        for (int i = 0; i < 4; i++) {
            int r = ih * 64 + (ty << 2) + i;
            int e = bm + r;
            int j = enb[e];
#pragma unroll
            for (int jh = 0; jh < 2; jh++) {
                int cb = jh * 64 + (tx << 2);
                float4 kv = *(const float4*)(g_Kn + (size_t)j * QKN + qoff + cb);
                float qs = acc[ih * 4 + i][jh * 4 + 0] * kv.x
                         + acc[ih * 4 + i][jh * 4 + 1] * kv.y
                         + acc[ih * 4 + i][jh * 4 + 2] * kv.z
                         + acc[ih * 4 + i][jh * 4 + 3] * kv.w;
                atomicAdd(&g_scores[e * 16 + ((qoff + cb) >> 4)], 4.0f * qs);
            }
        }
        return;
    }

    // ================= tensor path: tiles 0..6 (dh/env/lin) ==================
    const int wid = tid >> 5, lane = tid & 31;
    const int gid = lane >> 2, tig = lane & 3;
    const int tenid = (bid / 3) * 2 + sel;   // 0..2047
    const int bm = tenid << 5;               // 32 edges
    const uint32_t sb = smem_u32(smem);
    int* s_j   = (int*)(smem + OFF_J);
    int* s_ct  = (int*)(smem + OFF_CT);
    float* Xs  = (float*)(smem + OFF_XS);

    // cp.async B(0)
    for (int idx = tid; idx < 128 * 16; idx += 256) {
        int kk = idx >> 4, n8 = (idx & 15) << 3;
        uint32_t boff = (uint32_t)(kk * (LDN * 2) + n8 * 2);
        CP_ASYNC16(sb + OFF_BHI + boff, g_Whi + kk * 128 + n8);
        CP_ASYNC16(sb + OFF_BLO + boff, g_Wlo + kk * 128 + n8);
    }
    CP_COMMIT();

    if (tid < 32) { s_j[tid] = enb[bm + tid]; s_ct[tid] = ectr[bm + tid]; }
    for (int idx = tid; idx < 32 * 144; idx += 256) {
        int r = idx / 144, cc = idx % 144;
        Xs[r * 148 + cc] = X[(size_t)enb[bm + r] * 144 + cc];
    }
    for (int idx = tid; idx < 32 * 32; idx += 256) {
        int r = idx >> 5, c4 = (idx & 31) << 2;
        float4 v = *(const float4*)(T + (size_t)(bm + r) * 128 + c4);
        float lx, ly, lz, lw;
        uint32_t h01 = pack_hi2(v.x, v.y, lx, ly);
        uint32_t h23 = pack_hi2(v.z, v.w, lz, lw);
        int boff = r * (LDK * 2) + c4 * 2;
        *(uint2*)(smem + OFF_AHI + boff) = make_uint2(h01, h23);
        *(uint2*)(smem + OFF_ALO + boff) = make_uint2(pack_bf2(lx, ly), pack_bf2(lz, lw));
    }
    __syncthreads();

    const int wm = (wid & 1) << 4;
    const int wn = (wid >> 1) << 5;
    const int rr0 = wm + gid, rr1 = rr0 + 8;
    const int arow = wm + (lane & 15);
    const int acolb = ((lane >> 4) << 3) * 2;
    const int j0 = s_j[rr0], j1 = s_j[rr1];
    const int ct0 = s_ct[rr0], ct1 = s_ct[rr1];

    for (int tile = 0; tile < 7; tile++) {
        int base = tile * 128;
        int width = (tile == 6) ? 48 : 128;

        // hoisted U gathers (latency hidden under wait+mainloop)
        float2 u0v[4], u1v[4];
#pragma unroll
        for (int ni = 0; ni < 4; ni++) {
            int c = wn + (ni << 3) + (tig << 1);
            u0v[ni] = make_float2(0.f, 0.f);
            u1v[ni] = make_float2(0.f, 0.f);
            if (c < width) {
                u0v[ni] = __ldg((const float2*)(g_U + (size_t)j0 * UCOLS + base + c));
                u1v[ni] = __ldg((const float2*)(g_U + (size_t)j1 * UCOLS + base + c));
            }
        }

        CP_WAIT0();
        __syncthreads();

        float acc[4][4];
#pragma unroll
        for (int ni = 0; ni < 4; ni++)
#pragma unroll
            for (int q = 0; q < 4; q++) acc[ni][q] = 0.f;

#pragma unroll
        for (int ks = 0; ks < 8; ks++) {
            const int k0 = ks << 4;
            uint32_t ahi[4], alo[4];
            const uint32_t aaddr = (uint32_t)(arow * (LDK * 2) + k0 * 2 + acolb);
            ldsm_x4(ahi, sb + OFF_AHI + aaddr);
            ldsm_x4(alo, sb + OFF_ALO + aaddr);
            const uint32_t rowb = (uint32_t)((k0 + (lane & 15)) * (LDN * 2) + ((lane >> 4) << 4));
#pragma unroll
            for (int ni = 0; ni < 4; ni += 2) {
                const uint32_t nb = (uint32_t)((wn + (ni << 3)) * 2);
                uint32_t bh[4], bl[4];
                ldsm_x4_trans(bh, sb + OFF_BHI + rowb + nb);
                ldsm_x4_trans(bl, sb + OFF_BLO + rowb + nb);
                mma16816(acc[ni],   ahi, bh);     mma16816(acc[ni],   ahi, bl);
                mma16816(acc[ni],   alo, bh);
                mma16816(acc[ni+1], ahi, bh + 2); mma16816(acc[ni+1], ahi, bl + 2);
                mma16816(acc[ni+1], alo, bh + 2);
            }
        }
        __syncthreads();

        if (tile < 6) {
            const __nv_bfloat16* sh = g_Whi + (size_t)(tile + 1) * 16384;
            const __nv_bfloat16* sl = g_Wlo + (size_t)(tile + 1) * 16384;
            for (int idx = tid; idx < 128 * 16; idx += 256) {
                int kk = idx >> 4, n8 = (idx & 15) << 3;
                uint32_t boff = (uint32_t)(kk * (LDN * 2) + n8 * 2);
                CP_ASYNC16(sb + OFF_BHI + boff, sh + kk * 128 + n8);
                CP_ASYNC16(sb + OFF_BLO + boff, sl + kk * 128 + n8);
            }
            CP_COMMIT();
        }

        const int e0 = bm + rr0, e1 = bm + rr1;
        float gv[4][4];
#pragma unroll
        for (int ni = 0; ni < 4; ni++) {
            int c = wn + (ni << 3) + (tig << 1);
            if (c < width) {
                gv[ni][0] = acc[ni][0] * u0v[ni].x; gv[ni][1] = acc[ni][1] * u0v[ni].y;
                gv[ni][2] = acc[ni][2] * u1v[ni].x; gv[ni][3] = acc[ni][3] * u1v[ni].y;
                if (tile == 0) {
                    atomicAdd(&g_dh[ct0 * 128 + c + 0], gv[ni][0]);
                    atomicAdd(&g_dh[ct0 * 128 + c + 1], gv[ni][1]);
                    atomicAdd(&g_dh[ct1 * 128 + c + 0], gv[ni][2]);
                    atomicAdd(&g_dh[ct1 * 128 + c + 1], gv[ni][3]);
                    if (c < ENVN) {
                        *(float2*)(g_envw + (size_t)e0 * ENVN + c) = make_float2(gv[ni][0], gv[ni][1]);
                        *(float2*)(g_envw + (size_t)e1 * ENVN + c) = make_float2(gv[ni][2], gv[ni][3]);
                    }
                }
            } else {
                gv[ni][0] = gv[ni][1] = gv[ni][2] = gv[ni][3] = 0.f;
            }
        }

        // lin groups -> g_x (lin term only; env term added in alpha_scatter)
#pragma unroll
        for (int p = 0; p < 2; p++) {
            int gc0 = base + wn + (p << 4);
            if (gc0 >= ENVN && gc0 < UCOLS) {
                int g16 = (gc0 - ENVN) >> 4;
                int ir = g16 >> 4, u = g16 & 15;
                int doff = (ir == 0) ? 0 : ((ir == 1) ? 1 : 4);
                int nd = (ir == 0) ? 1 : ((ir == 1) ? 3 : 5);
                int v0 = tig << 1, v1 = (tig << 1) + 8;
#pragma unroll
                for (int row = 0; row < 2; row++) {
                    int rr = row ? rr1 : rr0;
                    const float* xr = Xs + rr * 148;
                    float part[5];
#pragma unroll
                    for (int dd = 0; dd < 5; dd++) {
                        if (dd >= nd) break;
                        int d = doff + dd;
                        part[dd] = gv[2*p][row*2]     * xr[v0*9 + d]
                                 + gv[2*p][row*2+1]   * xr[(v0+1)*9 + d]
                                 + gv[2*p+1][row*2]   * xr[v1*9 + d]
                                 + gv[2*p+1][row*2+1] * xr[(v1+1)*9 + d];
                    }
#pragma unroll
                    for (int dd = 0; dd < 5; dd++) {
                        if (dd >= nd) break;
                        part[dd] += __shfl_xor_sync(0xFFFFFFFFu, part[dd], 1);
                        part[dd] += __shfl_xor_sync(0xFFFFFFFFu, part[dd], 2);
                    }
                    if (tig == 0) {
                        float* xo = g_x + (size_t)(bm + rr) * 144 + u * 9;
#pragma unroll
                        for (int dd = 0; dd < 5; dd++) {
                            if (dd >= nd) break;
                            xo[doff + dd] = 0.25f * part[dd];
                        }
                    }
                }
            }
        }
    }
}

// ---------- scatter softmax ----------
__global__ void smax_kernel(const int* __restrict__ ectr) {
    int idx = blockIdx.x * blockDim.x + threadIdx.x;
    int e = idx >> 4, m = idx & 15;
    atomicMax(&g_maxb[ectr[e] * 16 + m], fenc(g_scores[idx]));
}

__global__ void sexp_kernel(const int* __restrict__ ectr) {
    int idx = blockIdx.x * blockDim.x + threadIdx.x;
    int e = idx >> 4, m = idx & 15;
    int ct = ectr[e];
    float mx = fdec(g_maxb[ct * 16 + m]);
    float ex = expf(g_scores[idx] - mx);
    g_scores[idx] = ex;
    atomicAdd(&g_den[ct * 16 + m], ex);
}

// ---------- alpha scatter: dX[ct] += (x_lin + sph (x) env) * alpha ----------
__global__ void __launch_bounds__(256) alpha_scatter_kernel(
    const int* __restrict__ ectr, const float* __restrict__ sph)
{
    __shared__ float sal[8][16];
    __shared__ float sev[8][48];
    __shared__ float ssp[8][12];
    const int warp = threadIdx.x >> 5;
    const int lane = threadIdx.x & 31;
    const int e = blockIdx.x * 8 + warp;
    const int ct = ectr[e];
    if (lane < 16) {
        float ex = g_scores[e * 16 + lane];
        float dn = g_den[ct * 16 + lane];
        sal[warp][lane] = ex / (dn + 1e-20f);
    }
    if (lane < 9) ssp[warp][lane] = sph[(size_t)e * 9 + lane];
    for (int t = lane; t < 48; t += 32) sev[warp][t] = g_envw[(size_t)e * 48 + t];
    __syncwarp();
    const float* xr = g_x + (size_t)e * 144;
#pragma unroll
    for (int k = 0; k < 5; k++) {
        int idx = lane + k * 32;
        if (idx < 144) {
            int u = idx / 9, d = idx % 9;
            int ir = (d == 0) ? 0 : ((d < 4) ? 1 : 2);
            float v = xr[idx] + ssp[warp][d] * sev[warp][ir * 16 + u];
            atomicAdd(&g_dX[(size_t)ct * 144 + idx], v * sal[warp][u]);
        }
    }
}

// ---------- node finalize: layernorm(h + dh) ----------
__global__ void node_h_kernel(const float* __restrict__ h,
                              const float* __restrict__ gam,
                              const float* __restrict__ bet,
                              float* __restrict__ out)
{
    int n = blockIdx.x * 8 + (threadIdx.x >> 5);
    int lane = threadIdx.x & 31;
    float4 hv = *(const float4*)(h + (size_t)n * 128 + lane * 4);
    float4 dv = *(const float4*)(g_dh + (size_t)n * 128 + lane * 4);
    float v[4] = {hv.x + dv.x, hv.y + dv.y, hv.z + dv.z, hv.w + dv.w};
    float s = 0.f, sq = 0.f;
#pragma unroll
    for (int k = 0; k < 4; k++) { s += v[k]; sq += v[k] * v[k]; }
#pragma unroll
    for (int o = 16; o; o >>= 1) {
        s  += __shfl_xor_sync(0xFFFFFFFFu, s, o);
        sq += __shfl_xor_sync(0xFFFFFFFFu, sq, o);
    }
    float mu = s * (1.f / 128.f);
    float var = sq * (1.f / 128.f) - mu * mu;
    float inv = rsqrtf(var + EPSF);
    float4 ov;
    ov.x = (v[0] - mu) * inv * gam[lane * 4 + 0] + bet[lane * 4 + 0];
    ov.y = (v[1] - mu) * inv * gam[lane * 4 + 1] + bet[lane * 4 + 1];
    ov.z = (v[2] - mu) * inv * gam[lane * 4 + 2] + bet[lane * 4 + 2];
    ov.w = (v[3] - mu) * inv * gam[lane * 4 + 3] + bet[lane * 4 + 3];
    *(float4*)(out + (size_t)n * 128 + lane * 4) = ov;
}

// ---------- node finalize: so3_layernorm(X + dX) ----------
__global__ void node_X_kernel(const float* __restrict__ Xin,
                              float* __restrict__ out)
{
    int n = blockIdx.x * 8 + (threadIdx.x >> 5);
    int lane = threadIdx.x & 31;
    float vals[5];
    float s0 = 0.f, s1 = 0.f, s2 = 0.f;
    int k = 0;
    for (int t = lane; t < 144; t += 32, k++) {
        float v = Xin[(size_t)n * 144 + t] + g_dX[(size_t)n * 144 + t];
        vals[k] = v;
        int s = t % 9;
        if (s == 0) s0 += v * v;
        else if (s < 4) s1 += v * v;
        else s2 += v * v;
    }
#pragma unroll
    for (int o = 16; o; o >>= 1) {
        s0 += __shfl_xor_sync(0xFFFFFFFFu, s0, o);
        s1 += __shfl_xor_sync(0xFFFFFFFFu, s1, o);
        s2 += __shfl_xor_sync(0xFFFFFFFFu, s2, o);
    }
    float i0 = rsqrtf(s0 * (1.f / 16.f) + EPSF);
    float i1 = rsqrtf(s1 * (1.f / 48.f) + EPSF);
    float i2 = rsqrtf(s2 * (1.f / 80.f) + EPSF);
    k = 0;
    for (int t = lane; t < 144; t += 32, k++) {
        int s = t % 9;
        float inv = (s == 0) ? i0 : ((s < 4) ? i1 : i2);
        out[(size_t)n * 144 + t] = vals[k] * inv;
    }
}

// ---------- copy t_ij to output tail ----------
__global__ void copy_t_kernel(const float* __restrict__ src, float* __restrict__ dst) {
    size_t i = (size_t)blockIdx.x * blockDim.x + threadIdx.x;
    ((float4*)dst)[i] = ((const float4*)src)[i];
}

extern "C" void kernel_launch(void* const* d_in, const int* in_sizes, int n_in,
                              void* d_out, int out_size) {
    const float* h      = (const float*)d_in[0];
    const float* X      = (const float*)d_in[1];
    const float* t_ij   = (const float*)d_in[2];
    const float* sph    = (const float*)d_in[3];
    const int*   ectr   = (const int*)d_in[5];
    const int*   enb    = (const int*)d_in[6];
    const float* W_rs   = (const float*)d_in[7];
    const float* W1     = (const float*)d_in[8];
    const float* W2     = (const float*)d_in[9];
    const float* gam    = (const float*)d_in[10];
    const float* bet    = (const float*)d_in[11];
    const float* W_q    = (const float*)d_in[12];
    const float* W_k    = (const float*)d_in[13];
    float* out = (float*)d_out;

    cudaFuncSetAttribute(edge_hybrid_kernel,
                         cudaFuncAttributeMaxDynamicSharedMemorySize, SMEM_EDGE);
    cudaFuncSetAttribute(node_mma_kernel,
                         cudaFuncAttributeMaxDynamicSharedMemorySize, SMEM_NODE);

    init_kernel<<<2048, 256>>>();
    wprep_kernel<<<304, 256>>>(W_rs, W_q, W1, W_k, W2);
    node_mma_kernel<<<128, 512, SMEM_NODE>>>(h);
    edge_hybrid_kernel<<<3072, 256, SMEM_EDGE>>>(t_ij, ectr, enb, X, W_q);
    smax_kernel<<<EE * 16 / 256, 256>>>(ectr);
    sexp_kernel<<<EE * 16 / 256, 256>>>(ectr);
    alpha_scatter_kernel<<<EE / 8, 256>>>(ectr, sph);
    node_h_kernel<<<NN / 8, 256>>>(h, gam, bet, out);
    node_X_kernel<<<NN / 8, 256>>>(X, out + (size_t)NN * 128);
    copy_t_kernel<<<(EE * 128 / 4) / 256, 256>>>(t_ij, out + (size_t)NN * 128 + (size_t)NN * 144);
}

// round 17
// speedup vs baseline: 1.1208x; 1.1208x over previous
#include <cuda_runtime.h>
#include <cuda_bf16.h>
#include <stdint.h>
#include <math.h>

#define NN 8192
#define EE 65536
#define LAT 128
#define WRS_LD 944
#define UCOLS 816
#define ENVN 48
#define MULN 16
#define SPHN 9
#define QKN 256
#define EPSF 1e-5f

// ---------- static scratch ----------
__device__ float    g_U[NN * UCOLS];
__device__ float    g_Kn[NN * QKN];
__device__ float    g_dh[NN * LAT];
__device__ float    g_x[(size_t)EE * 144];
__device__ float    g_scores[EE * MULN];
__device__ unsigned g_maxb[NN * MULN];
__device__ float    g_den[NN * MULN];
__device__ float    g_dX[NN * MULN * SPHN];
// bf16 hi/lo tiles for the node kernel (9..18); tf32 tiles 0..8 for edges
__device__ __nv_bfloat16 g_Whi[19 * 128 * 128];
__device__ __nv_bfloat16 g_Wlo[19 * 128 * 128];
__device__ uint32_t g_Wt32[9 * 128 * 128];

__device__ __forceinline__ unsigned fenc(float f) {
    unsigned u = __float_as_uint(f);
    return (u & 0x80000000u) ? ~u : (u | 0x80000000u);
}
__device__ __forceinline__ float fdec(unsigned u) {
    return (u & 0x80000000u) ? __uint_as_float(u & 0x7FFFFFFFu)
                             : __uint_as_float(~u);
}
__device__ __forceinline__ uint32_t f2tf32(float f) {
    uint32_t u;
    asm("cvt.rna.tf32.f32 %0, %1;" : "=r"(u) : "f"(f));
    return u;
}

__global__ void init_kernel() {
    int i = blockIdx.x * blockDim.x + threadIdx.x;
    int stride = gridDim.x * blockDim.x;
    for (int t = i; t < NN * LAT; t += stride) g_dh[t] = 0.f;
    for (int t = i; t < NN * MULN; t += stride) { g_den[t] = 0.f; g_maxb[t] = 0u; }
    for (int t = i; t < NN * MULN * SPHN; t += stride) g_dX[t] = 0.f;
}

__device__ __forceinline__ uint32_t pack_hi2(float x, float y, float& lx, float& ly) {
    __nv_bfloat16 bx = __float2bfloat16(x), by = __float2bfloat16(y);
    lx = x - __bfloat162float(bx);
    ly = y - __bfloat162float(by);
    return ((uint32_t)__bfloat16_as_ushort(by) << 16) | __bfloat16_as_ushort(bx);
}
__device__ __forceinline__ uint32_t pack_bf2(float x, float y) {
    return ((uint32_t)__bfloat16_as_ushort(__float2bfloat16(y)) << 16)
         | __bfloat16_as_ushort(__float2bfloat16(x));
}

// ---------- one-time W conversion ----------
__global__ void wprep_kernel(const float* __restrict__ Wrs, const float* __restrict__ Wq,
                             const float* __restrict__ W1,  const float* __restrict__ Wk,
                             const float* __restrict__ W2) {
    int idx = blockIdx.x * blockDim.x + threadIdx.x;
    if (idx >= 19 * 128 * 32) return;
    int tile = idx >> 12;
    int rem = idx & 4095;
    int kk = rem >> 5, n4 = (rem & 31) << 2;
    int width = 128;
    const float* src = nullptr;
    size_t ld = 0; int base = 0;
    if (tile < 7)       { src = Wrs; ld = WRS_LD; base = tile * 128; if (tile == 6) width = 48; }
    else if (tile < 9)  { src = Wq;  ld = QKN;    base = (tile - 7) * 128; }
    else if (tile == 9) { src = W1;  ld = 128;    base = 0; }
    else if (tile < 12) { src = Wk;  ld = QKN;    base = (tile - 10) * 128; }
    else                { src = W2;  ld = WRS_LD; base = (tile - 12) * 128; if (tile == 18) width = 48; }
    float4 w = make_float4(0.f, 0.f, 0.f, 0.f);
    if (n4 < width) w = *(const float4*)(src + (size_t)kk * ld + base + n4);
    float lx, ly, lz, lw;
    uint32_t h01 = pack_hi2(w.x, w.y, lx, ly);
    uint32_t h23 = pack_hi2(w.z, w.w, lz, lw);
    size_t o = (size_t)tile * 16384 + kk * 128 + n4;
    *(uint2*)(g_Whi + o) = make_uint2(h01, h23);
    *(uint2*)(g_Wlo + o) = make_uint2(pack_bf2(lx, ly), pack_bf2(lz, lw));
    if (tile < 9) {
        g_Wt32[o + 0] = f2tf32(w.x);
        g_Wt32[o + 1] = f2tf32(w.y);
        g_Wt32[o + 2] = f2tf32(w.z);
        g_Wt32[o + 3] = f2tf32(w.w);
    }
}

// ============================================================
// MMA helpers
// ============================================================
__device__ __forceinline__ void mma16816(float* c, const uint32_t* a, const uint32_t* b) {
    asm volatile(
        "mma.sync.aligned.m16n8k16.row.col.f32.bf16.bf16.f32 "
        "{%0,%1,%2,%3}, {%4,%5,%6,%7}, {%8,%9}, {%0,%1,%2,%3};"
        : "+f"(c[0]), "+f"(c[1]), "+f"(c[2]), "+f"(c[3])
        : "r"(a[0]), "r"(a[1]), "r"(a[2]), "r"(a[3]), "r"(b[0]), "r"(b[1]));
}
__device__ __forceinline__ void mma_tf32(float* c, uint32_t a0, uint32_t a1,
                                         uint32_t a2, uint32_t a3,
                                         uint32_t b0, uint32_t b1) {
    asm volatile(
        "mma.sync.aligned.m16n8k8.row.col.f32.tf32.tf32.f32 "
        "{%0,%1,%2,%3}, {%4,%5,%6,%7}, {%8,%9}, {%0,%1,%2,%3};"
        : "+f"(c[0]), "+f"(c[1]), "+f"(c[2]), "+f"(c[3])
        : "r"(a0), "r"(a1), "r"(a2), "r"(a3), "r"(b0), "r"(b1));
}
__device__ __forceinline__ void ldsm_x4_trans(uint32_t* d, uint32_t addr) {
    asm volatile("ldmatrix.sync.aligned.m8n8.x4.trans.shared.b16 {%0,%1,%2,%3}, [%4];"
                 : "=r"(d[0]), "=r"(d[1]), "=r"(d[2]), "=r"(d[3]) : "r"(addr));
}
__device__ __forceinline__ void ldsm_x4(uint32_t* d, uint32_t addr) {
    asm volatile("ldmatrix.sync.aligned.m8n8.x4.shared.b16 {%0,%1,%2,%3}, [%4];"
                 : "=r"(d[0]), "=r"(d[1]), "=r"(d[2]), "=r"(d[3]) : "r"(addr));
}
__device__ __forceinline__ uint32_t smem_u32(const void* p) {
    uint32_t a;
    asm("{ .reg .u64 t; cvta.to.shared.u64 t, %1; cvt.u32.u64 %0, t; }" : "=r"(a) : "l"(p));
    return a;
}
#define CP_ASYNC16(dst, src) \
    asm volatile("cp.async.cg.shared.global [%0], [%1], 16;" :: "r"(dst), "l"(src))
#define CP_COMMIT() asm volatile("cp.async.commit_group;" ::: "memory")
#define CP_WAIT0()  asm volatile("cp.async.wait_group 0;" ::: "memory")

#define LDK 136
#define LDN 136

// ============================================================
// fused node kernel (bf16 3-pass, unchanged from R13)
// ============================================================
#define NATB (64 * LDK * 2)
#define NBTB (128 * LDN * 2)
#define NOFF_AHI  0
#define NOFF_ALO  (NOFF_AHI + NATB)
#define NOFF_SHI  (NOFF_ALO + NATB)
#define NOFF_SLO  (NOFF_SHI + NATB)
#define NOFF_BHI  (NOFF_SLO + NATB)
#define NOFF_BLO  (NOFF_BHI + NBTB)
#define SMEM_NODE (NOFF_BLO + NBTB)

__global__ void __launch_bounds__(512, 1) node_mma_kernel(const float* __restrict__ h)
{
    extern __shared__ char smem[];
    const int tid = threadIdx.x, wid = tid >> 5, lane = tid & 31;
    const int gid = lane >> 2, tig = lane & 3;
    const int bm = blockIdx.x << 6;
    const uint32_t sb = smem_u32(smem);

    for (int idx = tid; idx < 64 * 32; idx += 512) {
        int r = idx >> 5, c4 = (idx & 31) << 2;
        float4 v = *(const float4*)(h + (size_t)(bm + r) * 128 + c4);
        float lx, ly, lz, lw;
        uint32_t h01 = pack_hi2(v.x, v.y, lx, ly);
        uint32_t h23 = pack_hi2(v.z, v.w, lz, lw);
        int boff = r * (LDK * 2) + c4 * 2;
        *(uint2*)(smem + NOFF_AHI + boff) = make_uint2(h01, h23);
        *(uint2*)(smem + NOFF_ALO + boff) = make_uint2(pack_bf2(lx, ly), pack_bf2(lz, lw));
    }

    const int wm = (wid & 3) << 4;
    const int wn = (wid >> 2) << 5;
    const int rr0 = wm + gid, rr1 = rr0 + 8;
    const int arow = wm + (lane & 15);
    const int acolb = ((lane >> 4) << 3) * 2;

    for (int ph = 0; ph < 10; ph++) {
        int wtile;
        uint32_t aoffH, aoffL;
        if (ph == 0)      { wtile = 9;            aoffH = NOFF_AHI; aoffL = NOFF_ALO; }
        else if (ph < 8)  { wtile = 12 + ph - 1;  aoffH = NOFF_SHI; aoffL = NOFF_SLO; }
        else              { wtile = 10 + ph - 8;  aoffH = NOFF_AHI; aoffL = NOFF_ALO; }
        int width = (wtile == 18) ? 48 : 128;

        {
            const __nv_bfloat16* sh = g_Whi + (size_t)wtile * 16384;
            const __nv_bfloat16* sl = g_Wlo + (size_t)wtile * 16384;
            for (int idx = tid; idx < 128 * 16; idx += 512) {
                int kk = idx >> 4, n8 = (idx & 15) << 3;
                int boff = kk * (LDN * 2) + n8 * 2;
                *(uint4*)(smem + NOFF_BHI + boff) = *(const uint4*)(sh + kk * 128 + n8);
                *(uint4*)(smem + NOFF_BLO + boff) = *(const uint4*)(sl + kk * 128 + n8);
            }
        }
        __syncthreads();

        float acc[4][4];
#pragma unroll
        for (int ni = 0; ni < 4; ni++)
#pragma unroll
            for (int q = 0; q < 4; q++) acc[ni][q] = 0.f;

#pragma unroll
        for (int ks = 0; ks < 8; ks++) {
            const int k0 = ks << 4;
            uint32_t ahi[4], alo[4];
            const uint32_t aaddr = (uint32_t)(arow * (LDK * 2) + k0 * 2 + acolb);
            ldsm_x4(ahi, sb + aoffH + aaddr);
            ldsm_x4(alo, sb + aoffL + aaddr);
            const uint32_t rowb = (uint32_t)((k0 + (lane & 15)) * (LDN * 2) + ((lane >> 4) << 4));
#pragma unroll
            for (int ni = 0; ni < 4; ni += 2) {
                const uint32_t nb = (uint32_t)((wn + (ni << 3)) * 2);
                uint32_t bh[4], bl[4];
                ldsm_x4_trans(bh, sb + NOFF_BHI + rowb + nb);
                ldsm_x4_trans(bl, sb + NOFF_BLO + rowb + nb);
                mma16816(acc[ni],   ahi, bh);     mma16816(acc[ni],   ahi, bl);
                mma16816(acc[ni],   alo, bh);
                mma16816(acc[ni+1], ahi, bh + 2); mma16816(acc[ni+1], ahi, bl + 2);
                mma16816(acc[ni+1], alo, bh + 2);
            }
        }
        __syncthreads();

        if (ph == 0) {
#pragma unroll
            for (int ni = 0; ni < 4; ni++) {
                int c = wn + (ni << 3) + (tig << 1);
                float v0 = acc[ni][0] / (1.f + expf(-acc[ni][0]));
                float v1 = acc[ni][1] / (1.f + expf(-acc[ni][1]));
                float v2 = acc[ni][2] / (1.f + expf(-acc[ni][2]));
                float v3 = acc[ni][3] / (1.f + expf(-acc[ni][3]));
                float l0, l1, l2, l3;
                uint32_t h01 = pack_hi2(v0, v1, l0, l1);
                uint32_t h23 = pack_hi2(v2, v3, l2, l3);
                *(uint32_t*)(smem + NOFF_SHI + rr0 * (LDK*2) + c * 2) = h01;
                *(uint32_t*)(smem + NOFF_SHI + rr1 * (LDK*2) + c * 2) = h23;
                *(uint32_t*)(smem + NOFF_SLO + rr0 * (LDK*2) + c * 2) = pack_bf2(l0, l1);
                *(uint32_t*)(smem + NOFF_SLO + rr1 * (LDK*2) + c * 2) = pack_bf2(l2, l3);
            }
            __syncthreads();
        } else if (ph < 8) {
            int base = (ph - 1) * 128;
#pragma unroll
            for (int ni = 0; ni < 4; ni++) {
                int c = wn + (ni << 3) + (tig << 1);
                if (c < width) {
                    *(float2*)(g_U + (size_t)(bm + rr0) * UCOLS + base + c)
                        = make_float2(acc[ni][0], acc[ni][1]);
                    *(float2*)(g_U + (size_t)(bm + rr1) * UCOLS + base + c)
                        = make_float2(acc[ni][2], acc[ni][3]);
                }
            }
        } else {
            int base = (ph - 8) * 128;
#pragma unroll
            for (int ni = 0; ni < 4; ni++) {
                int c = wn + (ni << 3) + (tig << 1);
                *(float2*)(g_Kn + (size_t)(bm + rr0) * QKN + base + c)
                    = make_float2(acc[ni][0], acc[ni][1]);
                *(float2*)(g_Kn + (size_t)(bm + rr1) * QKN + base + c)
                    = make_float2(acc[ni][2], acc[ni][3]);
            }
        }
    }
}

// ============================================================
// edge kernel: tf32 single-pass, 32 edges/CTA, 256 thr, 2 CTAs/SM
// ============================================================
#define ELDK 132                            // A pad (words): banks 4g+t, conflict-free
#define ELDN 136                            // B pad (words): banks 8t+g, conflict-free
#define EOFF_J    0
#define EOFF_CT   128
#define EOFF_SPH  256                       // 32*12*4 = 1536
#define EOFF_A    1792                      // 32*132*4 = 16896
#define EOFF_B    (EOFF_A + 16896)          // 128*136*4 = 69632
#define EOFF_XS   (EOFF_B + 69632)          // 32*148*4 = 18944
#define EOFF_ENV  (EOFF_XS + 18944)         // 32*48*4 = 6144
#define SMEM_EDGE (EOFF_ENV + 6144)         // 113408

__global__ void __launch_bounds__(256, 2) edge_mma_kernel(
    const float* __restrict__ T, const int* __restrict__ ectr,
    const int* __restrict__ enb, const float* __restrict__ sph,
    const float* __restrict__ X)
{
    extern __shared__ char smem[];
    const int tid = threadIdx.x, wid = tid >> 5, lane = tid & 31;
    const int gid = lane >> 2, tig = lane & 3;
    const int bm = blockIdx.x << 5;
    const uint32_t sb = smem_u32(smem);
    int* s_j   = (int*)(smem + EOFF_J);
    int* s_ct  = (int*)(smem + EOFF_CT);
    float* sps = (float*)(smem + EOFF_SPH);
    uint32_t* As = (uint32_t*)(smem + EOFF_A);
    const uint32_t* Bs = (const uint32_t*)(smem + EOFF_B);
    float* Xs  = (float*)(smem + EOFF_XS);
    float* evs = (float*)(smem + EOFF_ENV);

    // cp.async B(0): 128 rows x 128 u32
    for (int idx = tid; idx < 128 * 32; idx += 256) {
        int kk = idx >> 5, n4 = (idx & 31) << 2;
        uint32_t boff = (uint32_t)(EOFF_B + (kk * ELDN + n4) * 4);
        CP_ASYNC16(sb + boff, g_Wt32 + kk * 128 + n4);
    }
    CP_COMMIT();

    if (tid < 32) { s_j[tid] = enb[bm + tid]; s_ct[tid] = ectr[bm + tid]; }
    for (int idx = tid; idx < 32 * 9; idx += 256)
        sps[(idx / 9) * 12 + (idx % 9)] = sph[(size_t)(bm + idx / 9) * 9 + (idx % 9)];
    for (int idx = tid; idx < 32 * 144; idx += 256) {
        int r = idx / 144, cc = idx % 144;
        Xs[r * 148 + cc] = X[(size_t)enb[bm + r] * 144 + cc];
    }
    // convert A -> tf32
    for (int idx = tid; idx < 32 * 32; idx += 256) {
        int r = idx >> 5, c4 = (idx & 31) << 2;
        float4 v = *(const float4*)(T + (size_t)(bm + r) * 128 + c4);
        uint32_t* dst = As + r * ELDK + c4;
        dst[0] = f2tf32(v.x); dst[1] = f2tf32(v.y);
        dst[2] = f2tf32(v.z); dst[3] = f2tf32(v.w);
    }
    __syncthreads();   // s_j/s_ct visible

    const int wm = (wid & 1) << 4;
    const int wn = (wid >> 1) << 5;
    const int rr0 = wm + gid, rr1 = rr0 + 8;
    const int j0 = s_j[rr0], j1 = s_j[rr1];
    const int ct0 = s_ct[rr0], ct1 = s_ct[rr1];
    const int e0 = bm + rr0, e1 = bm + rr1;
    const int arow0 = rr0 * ELDK, arow1 = rr1 * ELDK;

    for (int tile = 0; tile < 9; tile++) {
        int base = tile * 128;
        bool utile = tile < 7;
        int width = (tile == 6) ? 48 : 128;
        int qoff = (tile - 7) * 128;

        // hoisted gathers (latency hidden under wait+mainloop)
        float2 u0v[4], u1v[4];
#pragma unroll
        for (int ni = 0; ni < 4; ni++) {
            int c = wn + (ni << 3) + (tig << 1);
            u0v[ni] = make_float2(0.f, 0.f);
            u1v[ni] = make_float2(0.f, 0.f);
            if (utile) {
                if (c < width) {
                    u0v[ni] = __ldg((const float2*)(g_U + (size_t)j0 * UCOLS + base + c));
                    u1v[ni] = __ldg((const float2*)(g_U + (size_t)j1 * UCOLS + base + c));
                }
            } else {
                u0v[ni] = __ldg((const float2*)(g_Kn + (size_t)j0 * QKN + qoff + c));
                u1v[ni] = __ldg((const float2*)(g_Kn + (size_t)j1 * QKN + qoff + c));
            }
        }

        CP_WAIT0();
        __syncthreads();   // B(tile) ready

        float acc[4][4];
#pragma unroll
        for (int ni = 0; ni < 4; ni++)
#pragma unroll
            for (int q = 0; q < 4; q++) acc[ni][q] = 0.f;

#pragma unroll
        for (int ks = 0; ks < 16; ks++) {
            const int k0 = ks << 3;
            uint32_t a0 = As[arow0 + k0 + tig];
            uint32_t a1 = As[arow1 + k0 + tig];
            uint32_t a2 = As[arow0 + k0 + tig + 4];
            uint32_t a3 = As[arow1 + k0 + tig + 4];
            const int br0 = (k0 + tig) * ELDN;
            const int br1 = (k0 + tig + 4) * ELDN;
#pragma unroll
            for (int ni = 0; ni < 4; ni++) {
                int nn = wn + (ni << 3) + gid;
                uint32_t b0 = Bs[br0 + nn];
                uint32_t b1 = Bs[br1 + nn];
                mma_tf32(acc[ni], a0, a1, a2, a3, b0, b1);
            }
        }
        __syncthreads();   // all reads of B(tile) done

        // prefetch B(tile+1) under the epilogue
        if (tile < 8) {
            const uint32_t* wt = g_Wt32 + (size_t)(tile + 1) * 16384;
            for (int idx = tid; idx < 128 * 32; idx += 256) {
                int kk = idx >> 5, n4 = (idx & 31) << 2;
                uint32_t boff = (uint32_t)(EOFF_B + (kk * ELDN + n4) * 4);
                CP_ASYNC16(sb + boff, wt + kk * 128 + n4);
            }
            CP_COMMIT();
        }

        if (utile) {
            float gv[4][4];
#pragma unroll
            for (int ni = 0; ni < 4; ni++) {
                int c = wn + (ni << 3) + (tig << 1);
                if (c < width) {
                    gv[ni][0] = acc[ni][0] * u0v[ni].x; gv[ni][1] = acc[ni][1] * u0v[ni].y;
                    gv[ni][2] = acc[ni][2] * u1v[ni].x; gv[ni][3] = acc[ni][3] * u1v[ni].y;
                    if (tile == 0) {
                        atomicAdd(&g_dh[ct0 * 128 + c + 0], gv[ni][0]);
                        atomicAdd(&g_dh[ct0 * 128 + c + 1], gv[ni][1]);
                        atomicAdd(&g_dh[ct1 * 128 + c + 0], gv[ni][2]);
                        atomicAdd(&g_dh[ct1 * 128 + c + 1], gv[ni][3]);
                        if (c < ENVN) {
                            evs[rr0 * 48 + c] = gv[ni][0]; evs[rr0 * 48 + c + 1] = gv[ni][1];
                            evs[rr1 * 48 + c] = gv[ni][2]; evs[rr1 * 48 + c + 1] = gv[ni][3];
                        }
                    }
                } else {
                    gv[ni][0] = gv[ni][1] = gv[ni][2] = gv[ni][3] = 0.f;
                }
            }
            if (tile == 0) __syncthreads();

#pragma unroll
            for (int p = 0; p < 2; p++) {
                int gc0 = base + wn + (p << 4);
                if (gc0 >= ENVN && gc0 < UCOLS) {
                    int g16 = (gc0 - ENVN) >> 4;
                    int ir = g16 >> 4, u = g16 & 15;
                    int doff = (ir == 0) ? 0 : ((ir == 1) ? 1 : 4);
                    int nd = (ir == 0) ? 1 : ((ir == 1) ? 3 : 5);
                    int v0 = tig << 1, v1 = (tig << 1) + 8;
#pragma unroll
                    for (int row = 0; row < 2; row++) {
                        int rr = row ? rr1 : rr0;
                        const float* xr = Xs + rr * 148;
                        float part[5];
#pragma unroll
                        for (int dd = 0; dd < 5; dd++) {
                            if (dd >= nd) break;
                            int d = doff + dd;
                            part[dd] = gv[2*p][row*2]     * xr[v0*9 + d]
                                     + gv[2*p][row*2+1]   * xr[(v0+1)*9 + d]
                                     + gv[2*p+1][row*2]   * xr[v1*9 + d]
                                     + gv[2*p+1][row*2+1] * xr[(v1+1)*9 + d];
                        }
#pragma unroll
                        for (int dd = 0; dd < 5; dd++) {
                            if (dd >= nd) break;
                            part[dd] += __shfl_xor_sync(0xFFFFFFFFu, part[dd], 1);
                            part[dd] += __shfl_xor_sync(0xFFFFFFFFu, part[dd], 2);
                        }
                        if (tig == 0) {
                            float ev = evs[rr * 48 + ir * 16 + u];
                            float* xo = g_x + (size_t)(bm + rr) * 144 + u * 9;
#pragma unroll
                            for (int dd = 0; dd < 5; dd++) {
                                if (dd >= nd) break;
                                int d = doff + dd;
                                xo[d] = 0.25f * part[dd] + sps[rr * 12 + d] * ev;
                            }
                        }
                    }
                }
            }
        } else {
#pragma unroll
            for (int p = 0; p < 2; p++) {
                float s0 = 0.f, s1 = 0.f;
#pragma unroll
                for (int h2 = 0; h2 < 2; h2++) {
                    int ni = p * 2 + h2;
                    s0 += acc[ni][0] * u0v[ni].x + acc[ni][1] * u0v[ni].y;
                    s1 += acc[ni][2] * u1v[ni].x + acc[ni][3] * u1v[ni].y;
                }
                s0 += __shfl_xor_sync(0xFFFFFFFFu, s0, 1);
                s0 += __shfl_xor_sync(0xFFFFFFFFu, s0, 2);
                s1 += __shfl_xor_sync(0xFFFFFFFFu, s1, 1);
                s1 += __shfl_xor_sync(0xFFFFFFFFu, s1, 2);
                if (tig == 0) {
                    int m = (tile - 7) * 8 + (wn >> 4) + p;
                    g_scores[e0 * 16 + m] = 4.0f * s0;
                    g_scores[e1 * 16 + m] = 4.0f * s1;
                }
            }
        }
    }
}

// ---------- scatter softmax ----------
__global__ void smax_kernel(const int* __restrict__ ectr) {
    int idx = blockIdx.x * blockDim.x + threadIdx.x;
    int e = idx >> 4, m = idx & 15;
    atomicMax(&g_maxb[ectr[e] * 16 + m], fenc(g_scores[idx]));
}

__global__ void sexp_kernel(const int* __restrict__ ectr) {
    int idx = blockIdx.x * blockDim.x + threadIdx.x;
    int e = idx >> 4, m = idx & 15;
    int ct = ectr[e];
    float mx = fdec(g_maxb[ct * 16 + m]);
    float ex = expf(g_scores[idx] - mx);
    g_scores[idx] = ex;
    atomicAdd(&g_den[ct * 16 + m], ex);
}

// ---------- alpha scatter ----------
__global__ void __launch_bounds__(256) alpha_scatter_kernel(const int* __restrict__ ectr) {
    __shared__ float sal[8][16];
    const int warp = threadIdx.x >> 5;
    const int lane = threadIdx.x & 31;
    const int e = blockIdx.x * 8 + warp;
    const int ct = ectr[e];
    if (lane < 16) {
        float ex = g_scores[e * 16 + lane];
        float dn = g_den[ct * 16 + lane];
        sal[warp][lane] = ex / (dn + 1e-20f);
    }
    __syncwarp();
    const float* xr = g_x + (size_t)e * 144;
#pragma unroll
    for (int k = 0; k < 5; k++) {
        int idx = lane + k * 32;
        if (idx < 144) {
            int u = idx / 9;
            atomicAdd(&g_dX[(size_t)ct * 144 + idx], xr[idx] * sal[warp][u]);
        }
    }
}

// ---------- node finalize: layernorm(h + dh) ----------
__global__ void node_h_kernel(const float* __restrict__ h,
                              const float* __restrict__ gam,
                              const float* __restrict__ bet,
                              float* __restrict__ out)
{
    int n = blockIdx.x * 8 + (threadIdx.x >> 5);
    int lane = threadIdx.x & 31;
    float4 hv = *(const float4*)(h + (size_t)n * 128 + lane * 4);
    float4 dv = *(const float4*)(g_dh + (size_t)n * 128 + lane * 4);
    float v[4] = {hv.x + dv.x, hv.y + dv.y, hv.z + dv.z, hv.w + dv.w};
    float s = 0.f, sq = 0.f;
#pragma unroll
    for (int k = 0; k < 4; k++) { s += v[k]; sq += v[k] * v[k]; }
#pragma unroll
    for (int o = 16; o; o >>= 1) {
        s  += __shfl_xor_sync(0xFFFFFFFFu, s, o);
        sq += __shfl_xor_sync(0xFFFFFFFFu, sq, o);
    }
    float mu = s * (1.f / 128.f);
    float var = sq * (1.f / 128.f) - mu * mu;
    float inv = rsqrtf(var + EPSF);
    float4 ov;
    ov.x = (v[0] - mu) * inv * gam[lane * 4 + 0] + bet[lane * 4 + 0];
    ov.y = (v[1] - mu) * inv * gam[lane * 4 + 1] + bet[lane * 4 + 1];
    ov.z = (v[2] - mu) * inv * gam[lane * 4 + 2] + bet[lane * 4 + 2];
    ov.w = (v[3] - mu) * inv * gam[lane * 4 + 3] + bet[lane * 4 + 3];
    *(float4*)(out + (size_t)n * 128 + lane * 4) = ov;
}

// ---------- node finalize: so3_layernorm(X + dX) ----------
__global__ void node_X_kernel(const float* __restrict__ Xin,
                              float* __restrict__ out)
{
    int n = blockIdx.x * 8 + (threadIdx.x >> 5);
    int lane = threadIdx.x & 31;
    float vals[5];
    float s0 = 0.f, s1 = 0.f, s2 = 0.f;
    int k = 0;
    for (int t = lane; t < 144; t += 32, k++) {
        float v = Xin[(size_t)n * 144 + t] + g_dX[(size_t)n * 144 + t];
        vals[k] = v;
        int s = t % 9;
        if (s == 0) s0 += v * v;
        else if (s < 4) s1 += v * v;
        else s2 += v * v;
    }
#pragma unroll
    for (int o = 16; o; o >>= 1) {
        s0 += __shfl_xor_sync(0xFFFFFFFFu, s0, o);
        s1 += __shfl_xor_sync(0xFFFFFFFFu, s1, o);
        s2 += __shfl_xor_sync(0xFFFFFFFFu, s2, o);
    }
    float i0 = rsqrtf(s0 * (1.f / 16.f) + EPSF);
    float i1 = rsqrtf(s1 * (1.f / 48.f) + EPSF);
    float i2 = rsqrtf(s2 * (1.f / 80.f) + EPSF);
    k = 0;
    for (int t = lane; t < 144; t += 32, k++) {
        int s = t % 9;
        float inv = (s == 0) ? i0 : ((s < 4) ? i1 : i2);
        out[(size_t)n * 144 + t] = vals[k] * inv;
    }
}

// ---------- copy t_ij to output tail ----------
__global__ void copy_t_kernel(const float* __restrict__ src, float* __restrict__ dst) {
    size_t i = (size_t)blockIdx.x * blockDim.x + threadIdx.x;
    ((float4*)dst)[i] = ((const float4*)src)[i];
}

extern "C" void kernel_launch(void* const* d_in, const int* in_sizes, int n_in,
                              void* d_out, int out_size) {
    const float* h      = (const float*)d_in[0];
    const float* X      = (const float*)d_in[1];
    const float* t_ij   = (const float*)d_in[2];
    const float* sph    = (const float*)d_in[3];
    const int*   ectr   = (const int*)d_in[5];
    const int*   enb    = (const int*)d_in[6];
    const float* W_rs   = (const float*)d_in[7];
    const float* W1     = (const float*)d_in[8];
    const float* W2     = (const float*)d_in[9];
    const float* gam    = (const float*)d_in[10];
    const float* bet    = (const float*)d_in[11];
    const float* W_q    = (const float*)d_in[12];
    const float* W_k    = (const float*)d_in[13];
    float* out = (float*)d_out;

    cudaFuncSetAttribute(edge_mma_kernel,
                         cudaFuncAttributeMaxDynamicSharedMemorySize, SMEM_EDGE);
    cudaFuncSetAttribute(node_mma_kernel,
                         cudaFuncAttributeMaxDynamicSharedMemorySize, SMEM_NODE);

    init_kernel<<<2048, 256>>>();
    wprep_kernel<<<304, 256>>>(W_rs, W_q, W1, W_k, W2);
    node_mma_kernel<<<128, 512, SMEM_NODE>>>(h);
    edge_mma_kernel<<<2048, 256, SMEM_EDGE>>>(t_ij, ectr, enb, sph, X);
    smax_kernel<<<EE * 16 / 256, 256>>>(ectr);
    sexp_kernel<<<EE * 16 / 256, 256>>>(ectr);
    alpha_scatter_kernel<<<EE / 8, 256>>>(ectr);
    node_h_kernel<<<NN / 8, 256>>>(h, gam, bet, out);
    node_X_kernel<<<NN / 8, 256>>>(X, out + (size_t)NN * 128);
    copy_t_kernel<<<(EE * 128 / 4) / 256, 256>>>(t_ij, out + (size_t)NN * 128 + (size_t)NN * 144);
}